// round 1
// baseline (speedup 1.0000x reference)
#include <cuda_runtime.h>
#include <cstdint>

// Problem constants (fixed by the reference module)
#define DD   101   // DFS_WIDTH (inner dim)
#define KO   101   // output spectrum length
#define BM   128   // batch rows per block
#define NTHR 256
#define XT_STRIDE 130   // padded (even, odd-ish mod 32) stride for transposed x tile
#define AT_STRIDE 104   // padded stride for A^T rows

// A^T[d][k] (combined operator), padded to stride 104. 101*104 floats.
__device__ float g_At[DD * AT_STRIDE];

// ---------------------------------------------------------------------------
// Kernel 1: fold the four constant matrices into one operator.
// A[k,d] = ( sum_n Wre[k,n]*ReJ[n,d] - Wim[k,n]*ImJ[n,d] ) / 101
// Stored transposed: g_At[d*104 + k]. Padding columns zeroed.
// ---------------------------------------------------------------------------
__global__ void build_A_kernel(const float* __restrict__ Wre,
                               const float* __restrict__ Wim,
                               const float* __restrict__ ReJ,
                               const float* __restrict__ ImJ) {
    int d = blockIdx.x;      // 0..100
    int k = threadIdx.x;     // 0..127
    if (k >= AT_STRIDE) return;
    float acc = 0.0f;
    if (k < KO) {
        #pragma unroll 4
        for (int n = 0; n < DD; ++n) {
            acc = fmaf(Wre[k * DD + n],  ReJ[n * DD + d], acc);
            acc = fmaf(-Wim[k * DD + n], ImJ[n * DD + d], acc);
        }
        acc *= (1.0f / 101.0f);
    }
    g_At[d * AT_STRIDE + k] = acc;   // zeros in padding lanes
}

// ---------------------------------------------------------------------------
// Packed f32x2 helpers (Blackwell sm_100 family)
// ---------------------------------------------------------------------------
__device__ __forceinline__ void fma_f32x2(unsigned long long& acc,
                                          unsigned long long a,
                                          unsigned long long b) {
    asm("fma.rn.f32x2 %0, %1, %2, %0;" : "+l"(acc) : "l"(a), "l"(b));
}
__device__ __forceinline__ unsigned long long dup_f32x2(float v) {
    unsigned long long r;
    unsigned int u = __float_as_uint(v);
    asm("mov.b64 %0, {%1, %1};" : "=l"(r) : "r"(u));
    return r;
}

// ---------------------------------------------------------------------------
// Kernel 2: out[b,k] = sum_d A[k,d] * x[b,d]
// Block: 256 threads, BM=128 batch rows. kx = tid&15 covers k = kx+16i (7 i's,
// predicated at 101). by = tid>>4 covers b = by*8 + {0..7} as 4 f32x2 pairs.
// ---------------------------------------------------------------------------
extern __shared__ float sm_dyn[];

__global__ void __launch_bounds__(NTHR, 1)
fourier_gemm_kernel(const float* __restrict__ x, float* __restrict__ out) {
    float* xs = sm_dyn;                   // transposed: xs[d*130 + b], d<101, b<128
    float* as = sm_dyn + DD * XT_STRIDE;  // as[d*104 + k]

    const int tid = threadIdx.x;
    const long long brow = (long long)blockIdx.x * BM;

    // Stage x tile transposed (coalesced global reads; 2-way STS conflicts only).
    const float* xsrc = x + brow * DD;
    for (int i = tid; i < BM * DD; i += NTHR) {
        int r = i / DD;
        int c = i - r * DD;
        xs[c * XT_STRIDE + r] = xsrc[i];
    }
    // Stage A^T (L2-resident, contiguous).
    for (int i = tid; i < DD * AT_STRIDE; i += NTHR) {
        as[i] = g_At[i];
    }
    __syncthreads();

    const int kx = tid & 15;     // k base lane
    const int b0 = (tid >> 4) * 8;

    unsigned long long acc[7][4];
    #pragma unroll
    for (int i = 0; i < 7; ++i)
        #pragma unroll
        for (int p = 0; p < 4; ++p)
            acc[i][p] = 0ull;   // (0.0f, 0.0f)

    #pragma unroll 2
    for (int d = 0; d < DD; ++d) {
        const float* xrow = xs + d * XT_STRIDE + b0;  // even word offset -> LDS.64 ok
        unsigned long long xp[4];
        #pragma unroll
        for (int p = 0; p < 4; ++p)
            xp[p] = *reinterpret_cast<const unsigned long long*>(xrow + 2 * p);

        const float* arow = as + d * AT_STRIDE + kx;
        #pragma unroll
        for (int i = 0; i < 7; ++i) {
            unsigned long long ap = dup_f32x2(arow[16 * i]);
            #pragma unroll
            for (int p = 0; p < 4; ++p)
                fma_f32x2(acc[i][p], xp[p], ap);
        }
    }

    // Epilogue: out is [B, 101] row-major (trailing x1 dim is contiguous memory).
    #pragma unroll
    for (int i = 0; i < 7; ++i) {
        int k = kx + 16 * i;
        if (k < KO) {
            #pragma unroll
            for (int p = 0; p < 4; ++p) {
                unsigned int lo, hi;
                asm("mov.b64 {%0, %1}, %2;" : "=r"(lo), "=r"(hi) : "l"(acc[i][p]));
                long long b = brow + b0 + 2 * p;
                out[b * KO + k]       = __uint_as_float(lo);
                out[(b + 1) * KO + k] = __uint_as_float(hi);
            }
        }
    }
}

// ---------------------------------------------------------------------------
// Launch
// ---------------------------------------------------------------------------
extern "C" void kernel_launch(void* const* d_in, const int* in_sizes, int n_in,
                              void* d_out, int out_size) {
    const float* x   = (const float*)d_in[0];
    const float* Wre = (const float*)d_in[1];
    const float* Wim = (const float*)d_in[2];
    const float* ReJ = (const float*)d_in[3];
    const float* ImJ = (const float*)d_in[4];
    float* out = (float*)d_out;

    const int B = in_sizes[0] / DD;   // 262144

    build_A_kernel<<<DD, 128>>>(Wre, Wim, ReJ, ImJ);

    const int smem = (DD * XT_STRIDE + DD * AT_STRIDE) * (int)sizeof(float); // ~94.5 KB
    static bool attr_set = false;
    // Setting a func attribute is idempotent and not a stream op; safe under capture.
    cudaFuncSetAttribute(fourier_gemm_kernel,
                         cudaFuncAttributeMaxDynamicSharedMemorySize, smem);

    int grid = B / BM;               // 2048
    fourier_gemm_kernel<<<grid, NTHR, smem>>>(x, out);
    (void)attr_set; (void)n_in; (void)out_size;
}

// round 3
// speedup vs baseline: 1.0727x; 1.0727x over previous
#include <cuda_runtime.h>
#include <cuda_bf16.h>
#include <cstdint>

// ---------------------------------------------------------------------------
// Problem constants
// ---------------------------------------------------------------------------
#define DD    101          // logical inner dim and output dim
#define KO    101
#define KPAD  112          // K padded to 7*16
#define NROWS 104          // A operand rows (output cols padded to 13*8)
#define BM    128          // batch rows per CTA
#define NTHR  256

#define XSTRIDE_B 240      // bytes per X smem row (120 bf16): 15*16B -> conflict-free
#define ASTRIDE_B 240      // bytes per A smem row

// smem layout (bytes)
#define XH_OFF 0
#define XL_OFF 30720
#define AH_OFF 61440                 // 128*240*2
#define AL_OFF 86400                 // + 104*240
#define SMEM_BYTES 111360            // + 104*240
#define OUT_TILE_BYTES (BM * KO * 4) // 51712, staged over XH/XL region

#define A_IMG_BYTES (NROWS * XSTRIDE_B)   // 24960 per (hi|lo)

// Combined operator, bf16 hi/lo, row-major [n][k] with 240B row stride.
__device__ __align__(16) unsigned char g_Aimg[2 * A_IMG_BYTES];

// ---------------------------------------------------------------------------
// Helpers
// ---------------------------------------------------------------------------
__device__ __forceinline__ uint32_t smem_u32(const void* p) {
    uint32_t a;
    asm("{ .reg .u64 t; cvta.to.shared.u64 t, %1; cvt.u32.u64 %0, t; }"
        : "=r"(a) : "l"(p));
    return a;
}
__device__ __forceinline__ void ldsm_x4(uint32_t* r, uint32_t addr) {
    asm volatile("ldmatrix.sync.aligned.m8n8.x4.shared.b16 {%0,%1,%2,%3}, [%4];"
                 : "=r"(r[0]), "=r"(r[1]), "=r"(r[2]), "=r"(r[3]) : "r"(addr));
}
__device__ __forceinline__ void ldsm_x2(uint32_t* r, uint32_t addr) {
    asm volatile("ldmatrix.sync.aligned.m8n8.x2.shared.b16 {%0,%1}, [%2];"
                 : "=r"(r[0]), "=r"(r[1]) : "r"(addr));
}
__device__ __forceinline__ void mma_bf16(float* c, const uint32_t* a,
                                         const uint32_t* b) {
    asm volatile(
        "mma.sync.aligned.m16n8k16.row.col.f32.bf16.bf16.f32 "
        "{%0,%1,%2,%3}, {%4,%5,%6,%7}, {%8,%9}, {%0,%1,%2,%3};"
        : "+f"(c[0]), "+f"(c[1]), "+f"(c[2]), "+f"(c[3])
        : "r"(a[0]), "r"(a[1]), "r"(a[2]), "r"(a[3]), "r"(b[0]), "r"(b[1]));
}

// ---------------------------------------------------------------------------
// Kernel 1: fold constants -> combined operator -> bf16 hi/lo row-major image.
// A[n,d] = ( sum_m Wre[n,m]*ReJ[m,d] - Wim[n,m]*ImJ[m,d] ) / 101
// ---------------------------------------------------------------------------
__global__ void build_A_kernel(const float* __restrict__ Wre,
                               const float* __restrict__ Wim,
                               const float* __restrict__ ReJ,
                               const float* __restrict__ ImJ) {
    int n = blockIdx.x;       // 0..103
    int d = threadIdx.x;      // 0..127
    if (d >= XSTRIDE_B / 2) return;   // 120 cols per row
    float a = 0.0f;
    if (n < KO && d < DD) {
        float a0 = 0.f, a1 = 0.f;
        #pragma unroll 1
        for (int m = 0; m < DD - 1; m += 2) {
            a0 = fmaf(Wre[n*DD+m],   ReJ[m*DD+d],     a0);
            a0 = fmaf(-Wim[n*DD+m],  ImJ[m*DD+d],     a0);
            a1 = fmaf(Wre[n*DD+m+1], ReJ[(m+1)*DD+d], a1);
            a1 = fmaf(-Wim[n*DD+m+1], ImJ[(m+1)*DD+d], a1);
        }
        a0 = fmaf(Wre[n*DD+DD-1], ReJ[(DD-1)*DD+d], a0);
        a0 = fmaf(-Wim[n*DD+DD-1], ImJ[(DD-1)*DD+d], a0);
        a = (a0 + a1) * (1.0f / 101.0f);
    }
    __nv_bfloat16 hi = __float2bfloat16(a);
    __nv_bfloat16 lo = __float2bfloat16(a - __bfloat162float(hi));
    *(__nv_bfloat16*)(g_Aimg + n * ASTRIDE_B + d * 2)               = hi;
    *(__nv_bfloat16*)(g_Aimg + A_IMG_BYTES + n * ASTRIDE_B + d * 2) = lo;
}

// ---------------------------------------------------------------------------
// Kernel 2: out[128,101] tile = x[128,K] * A^T via mma.sync bf16 3-split.
// ---------------------------------------------------------------------------
extern __shared__ unsigned char smem[];

__global__ void __launch_bounds__(NTHR, 2)
fourier_mma_kernel(const float* __restrict__ x, float* __restrict__ out) {
    const int tid   = threadIdx.x;
    const int wid   = tid >> 5;
    const int lane  = tid & 31;
    const int mwarp = wid >> 1;     // 0..3  -> M rows [mwarp*32, +32)
    const int nhalf = wid & 1;      // 0..1  -> N cols [nhalf*56, +56)
    const uint32_t sbase = smem_u32(smem);
    const size_t brow = (size_t)blockIdx.x * BM;

    // ---- stage A images (contiguous copy) ----
    {
        const uint4* g = (const uint4*)g_Aimg;
        uint4* s = (uint4*)(smem + AH_OFF);
        #pragma unroll 4
        for (int i = tid; i < (2 * A_IMG_BYTES) / 16; i += NTHR) s[i] = g[i];
    }

    // ---- convert x tile -> bf16 hi/lo smem (56 col-pairs per row) ----
    {
        #pragma unroll 4
        for (int it = 0; it < (BM * 56) / NTHR; ++it) {   // 28 iters
            int idx = it * NTHR + tid;
            int r  = idx / 56;
            int cp = idx - r * 56;
            int gc = 2 * cp;
            const float* xr = x + (brow + (size_t)r) * DD;
            float v0 = (gc     < DD) ? __ldg(xr + gc)     : 0.0f;
            float v1 = (gc + 1 < DD) ? __ldg(xr + gc + 1) : 0.0f;
            __nv_bfloat16 h0 = __float2bfloat16(v0);
            __nv_bfloat16 h1 = __float2bfloat16(v1);
            __nv_bfloat16 l0 = __float2bfloat16(v0 - __bfloat162float(h0));
            __nv_bfloat16 l1 = __float2bfloat16(v1 - __bfloat162float(h1));
            uint32_t hp = ((uint32_t)__bfloat16_as_ushort(h1) << 16) | __bfloat16_as_ushort(h0);
            uint32_t lp = ((uint32_t)__bfloat16_as_ushort(l1) << 16) | __bfloat16_as_ushort(l0);
            uint32_t o = (uint32_t)r * XSTRIDE_B + (uint32_t)cp * 4;
            *(uint32_t*)(smem + XH_OFF + o) = hp;
            *(uint32_t*)(smem + XL_OFF + o) = lp;
        }
    }
    __syncthreads();

    // ---- mainloop ----
    float acc[2][7][4];
    #pragma unroll
    for (int mt = 0; mt < 2; ++mt)
        #pragma unroll
        for (int nt = 0; nt < 7; ++nt)
            #pragma unroll
            for (int i = 0; i < 4; ++i) acc[mt][nt][i] = 0.0f;

    // A-operand (x) ldmatrix base: row = mwarp*32 + lane%16, colhalf = lane/16
    const uint32_t xaddr = sbase + XH_OFF
        + (uint32_t)(mwarp * 32 + (lane & 15)) * XSTRIDE_B + (uint32_t)(lane >> 4) * 16;
    // B-operand (A) pair-load base: row = nhalf*56 + (lane/16)*8 + lane%8,
    //                               koff = ((lane/8)&1)*16
    const uint32_t baddr = sbase + AH_OFF
        + (uint32_t)(nhalf * 56 + ((lane >> 4) * 8) + (lane & 7)) * ASTRIDE_B
        + (uint32_t)(((lane >> 3) & 1) * 16);
    // nt6 x2 load: rows nhalf*56+48 + lane%8, koff = (lane/8 &1)*16 (lanes 0-15 used)
    const uint32_t baddr6 = sbase + AH_OFF
        + (uint32_t)(nhalf * 56 + 48 + (lane & 7)) * ASTRIDE_B
        + (uint32_t)(((lane >> 3) & 1) * 16);

    #pragma unroll 1
    for (int kt = 0; kt < KPAD / 16; ++kt) {
        const uint32_t ko = (uint32_t)kt * 32;
        uint32_t aH[2][4], aL[2][4];
        ldsm_x4(aH[0], xaddr + ko);
        ldsm_x4(aH[1], xaddr + 16 * XSTRIDE_B + ko);
        ldsm_x4(aL[0], xaddr + (XL_OFF - XH_OFF) + ko);
        ldsm_x4(aL[1], xaddr + (XL_OFF - XH_OFF) + 16 * XSTRIDE_B + ko);

        #pragma unroll
        for (int pr = 0; pr < 3; ++pr) {
            uint32_t bH[4], bL[4];
            ldsm_x4(bH, baddr + (uint32_t)pr * 16 * ASTRIDE_B + ko);
            ldsm_x4(bL, baddr + (AL_OFF - AH_OFF) + (uint32_t)pr * 16 * ASTRIDE_B + ko);
            #pragma unroll
            for (int mt = 0; mt < 2; ++mt) {
                mma_bf16(acc[mt][2*pr+0], aH[mt], bH + 0);
                mma_bf16(acc[mt][2*pr+0], aH[mt], bL + 0);
                mma_bf16(acc[mt][2*pr+0], aL[mt], bH + 0);
                mma_bf16(acc[mt][2*pr+1], aH[mt], bH + 2);
                mma_bf16(acc[mt][2*pr+1], aH[mt], bL + 2);
                mma_bf16(acc[mt][2*pr+1], aL[mt], bH + 2);
            }
        }
        if (nhalf == 0) {   // nt6 real only for cols 48..55; half1 nt6 is pad
            uint32_t bH[2], bL[2];
            ldsm_x2(bH, baddr6 + ko);
            ldsm_x2(bL, baddr6 + (AL_OFF - AH_OFF) + ko);
            #pragma unroll
            for (int mt = 0; mt < 2; ++mt) {
                mma_bf16(acc[mt][6], aH[mt], bH);
                mma_bf16(acc[mt][6], aH[mt], bL);
                mma_bf16(acc[mt][6], aL[mt], bH);
            }
        }
    }

    // ---- epilogue: stage exact [128 x 101] fp32 image, bulk-store ----
    __syncthreads();            // everyone done reading X region
    float* stage = (float*)smem;
    const int ntmax = (nhalf == 0) ? 7 : 6;
    #pragma unroll
    for (int mt = 0; mt < 2; ++mt) {
        const int r0 = mwarp * 32 + mt * 16 + (lane >> 2);
        #pragma unroll
        for (int nt = 0; nt < 7; ++nt) {
            if (nt >= ntmax) break;
            const int col = nhalf * 56 + nt * 8 + (lane & 3) * 2;
            float* d0 = stage + (size_t)r0 * KO;
            float* d1 = stage + (size_t)(r0 + 8) * KO;
            if (col < KO)     { d0[col]     = acc[mt][nt][0]; d1[col]     = acc[mt][nt][2]; }
            if (col + 1 < KO) { d0[col + 1] = acc[mt][nt][1]; d1[col + 1] = acc[mt][nt][3]; }
        }
    }
    __syncthreads();

    if (tid == 0) {
        asm volatile("fence.proxy.async.shared::cta;" ::: "memory");
        float* gdst = out + brow * KO;
        asm volatile("cp.async.bulk.global.shared::cta.bulk_group [%0], [%1], %2;"
                     :: "l"(gdst), "r"(sbase), "r"((uint32_t)OUT_TILE_BYTES) : "memory");
        asm volatile("cp.async.bulk.commit_group;" ::: "memory");
        asm volatile("cp.async.bulk.wait_group 0;" ::: "memory");
    }
}

// ---------------------------------------------------------------------------
// Launch
// ---------------------------------------------------------------------------
extern "C" void kernel_launch(void* const* d_in, const int* in_sizes, int n_in,
                              void* d_out, int out_size) {
    const float* x   = (const float*)d_in[0];
    const float* Wre = (const float*)d_in[1];
    const float* Wim = (const float*)d_in[2];
    const float* ReJ = (const float*)d_in[3];
    const float* ImJ = (const float*)d_in[4];
    float* out = (float*)d_out;

    const int B = in_sizes[0] / DD;   // 262144

    build_A_kernel<<<NROWS, 128>>>(Wre, Wim, ReJ, ImJ);

    cudaFuncSetAttribute(fourier_mma_kernel,
                         cudaFuncAttributeMaxDynamicSharedMemorySize, SMEM_BYTES);
    fourier_mma_kernel<<<B / BM, NTHR, SMEM_BYTES>>>(x, out);
    (void)n_in; (void)out_size;
}

// round 4
// speedup vs baseline: 1.6094x; 1.5002x over previous
#include <cuda_runtime.h>
#include <cuda_bf16.h>
#include <cstdint>

// ---------------------------------------------------------------------------
// Problem constants
// ---------------------------------------------------------------------------
#define DD    101          // inner dim (x cols)
#define KO    101          // output cols
#define BM    64           // batch rows per tile
#define NTHR  256
#define NROWS 104          // A rows padded (13*8)
#define ASTR  240          // A smem row stride bytes (120 bf16)
#define A_IMG_BYTES (NROWS * ASTR)     // 24960 per hi/lo

#define XSTR_W 120                     // raw X smem row stride in words (480 B)
#define RAW_BYTES (BM * XSTR_W * 4)    // 30720

// smem layout (bytes)
#define RAW0_OFF 0
#define RAW1_OFF 30720
#define AH_OFF   61440
#define AL_OFF   86400                 // AH_OFF + 24960
#define SMEM_BYTES 111360

#define GRID 296                       // 2 CTAs per SM on 148 SMs

__device__ __align__(16) unsigned char g_Aimg[2 * A_IMG_BYTES];

// ---------------------------------------------------------------------------
// Helpers
// ---------------------------------------------------------------------------
__device__ __forceinline__ uint32_t smem_u32(const void* p) {
    uint32_t a;
    asm("{ .reg .u64 t; cvta.to.shared.u64 t, %1; cvt.u32.u64 %0, t; }"
        : "=r"(a) : "l"(p));
    return a;
}
__device__ __forceinline__ void cp4(uint32_t dst, const void* src, uint32_t sz) {
    asm volatile("cp.async.ca.shared.global [%0], [%1], 4, %2;"
                 :: "r"(dst), "l"(src), "r"(sz) : "memory");
}
__device__ __forceinline__ void cp16(uint32_t dst, const void* src) {
    asm volatile("cp.async.cg.shared.global [%0], [%1], 16;"
                 :: "r"(dst), "l"(src) : "memory");
}
#define CP_COMMIT() asm volatile("cp.async.commit_group;" ::: "memory")
#define CP_WAIT1()  asm volatile("cp.async.wait_group 1;" ::: "memory")
#define CP_WAIT0()  asm volatile("cp.async.wait_group 0;" ::: "memory")

__device__ __forceinline__ float2 lds64(uint32_t a) {
    float2 v;
    asm volatile("ld.shared.v2.f32 {%0,%1}, [%2];" : "=f"(v.x), "=f"(v.y) : "r"(a));
    return v;
}
__device__ __forceinline__ void ldsm_x4(uint32_t* r, uint32_t addr) {
    asm volatile("ldmatrix.sync.aligned.m8n8.x4.shared.b16 {%0,%1,%2,%3}, [%4];"
                 : "=r"(r[0]), "=r"(r[1]), "=r"(r[2]), "=r"(r[3]) : "r"(addr));
}
__device__ __forceinline__ void ldsm_x2(uint32_t* r, uint32_t addr) {
    asm volatile("ldmatrix.sync.aligned.m8n8.x2.shared.b16 {%0,%1}, [%2];"
                 : "=r"(r[0]), "=r"(r[1]) : "r"(addr));
}
__device__ __forceinline__ void mma_bf16(float* c, const uint32_t* a,
                                         const uint32_t* b) {
    asm volatile(
        "mma.sync.aligned.m16n8k16.row.col.f32.bf16.bf16.f32 "
        "{%0,%1,%2,%3}, {%4,%5,%6,%7}, {%8,%9}, {%0,%1,%2,%3};"
        : "+f"(c[0]), "+f"(c[1]), "+f"(c[2]), "+f"(c[3])
        : "r"(a[0]), "r"(a[1]), "r"(a[2]), "r"(a[3]), "r"(b[0]), "r"(b[1]));
}
// fp32 pair -> bf16x2 hi + bf16x2 lo (residual), rn rounding
__device__ __forceinline__ void split2(float f0, float f1,
                                       uint32_t& hi, uint32_t& lo) {
    asm("cvt.rn.bf16x2.f32 %0, %1, %2;" : "=r"(hi) : "f"(f1), "f"(f0));
    float r0 = __uint_as_float(hi << 16);
    float r1 = __uint_as_float(hi & 0xffff0000u);
    float l0 = f0 - r0;
    float l1 = f1 - r1;
    asm("cvt.rn.bf16x2.f32 %0, %1, %2;" : "=r"(lo) : "f"(l1), "f"(l0));
}

// ---------------------------------------------------------------------------
// Kernel 1: fold constants -> combined operator -> bf16 hi/lo image (row-major
// [n][k], 240B stride). smem-staged so the dot products run at LDS latency.
// A[n,d] = ( sum_m Wre[n,m]*ReJ[m,d] - Wim[n,m]*ImJ[m,d] ) / 101
// ---------------------------------------------------------------------------
extern __shared__ float bsm[];
__global__ void build_A_kernel(const float* __restrict__ Wre,
                               const float* __restrict__ Wim,
                               const float* __restrict__ ReJ,
                               const float* __restrict__ ImJ) {
    float* sRe = bsm;                 // 10201
    float* sIm = bsm + 10201;         // 10201
    float* sW  = bsm + 20402;         // [2 rows Wre][2 rows Wim] = 404
    const int tid = threadIdx.x;      // 128 threads
    const int n0  = blockIdx.x * 2;   // 52 blocks -> n 0..103

    for (int i = tid; i < 10201; i += 128) { sRe[i] = ReJ[i]; sIm[i] = ImJ[i]; }
    for (int i = tid; i < 2 * DD; i += 128) {
        int j = i / DD, m = i - j * DD, n = n0 + j;
        sW[j * DD + m]          = (n < KO) ? Wre[n * DD + m] : 0.0f;
        sW[2 * DD + j * DD + m] = (n < KO) ? Wim[n * DD + m] : 0.0f;
    }
    __syncthreads();

    const int d = tid;
    if (d >= ASTR / 2) return;        // 120 cols per image row
    #pragma unroll 1
    for (int j = 0; j < 2; ++j) {
        const int n = n0 + j;
        float a = 0.0f;
        if (n < KO && d < DD) {
            float a0 = 0.f, a1 = 0.f;
            #pragma unroll 1
            for (int m = 0; m + 2 <= DD; m += 2) {
                a0 = fmaf(sW[j*DD+m],          sRe[m*DD+d],     a0);
                a0 = fmaf(-sW[2*DD+j*DD+m],    sIm[m*DD+d],     a0);
                a1 = fmaf(sW[j*DD+m+1],        sRe[(m+1)*DD+d], a1);
                a1 = fmaf(-sW[2*DD+j*DD+m+1],  sIm[(m+1)*DD+d], a1);
            }
            a0 = fmaf(sW[j*DD+DD-1],        sRe[(DD-1)*DD+d], a0);
            a0 = fmaf(-sW[2*DD+j*DD+DD-1],  sIm[(DD-1)*DD+d], a0);
            a = (a0 + a1) * (1.0f / 101.0f);
        }
        __nv_bfloat16 hi = __float2bfloat16(a);
        __nv_bfloat16 lo = __float2bfloat16(a - __bfloat162float(hi));
        *(__nv_bfloat16*)(g_Aimg + n * ASTR + d * 2)               = hi;
        *(__nv_bfloat16*)(g_Aimg + A_IMG_BYTES + n * ASTR + d * 2) = lo;
    }
}

// ---------------------------------------------------------------------------
// Kernel 2: persistent tiled GEMM, cp.async double-buffered raw x, in-register
// bf16 hi/lo split fused into the MMA mainloop.
// ---------------------------------------------------------------------------
extern __shared__ unsigned char smem[];

__device__ __forceinline__ void issue_tile(uint32_t sdst, const float* x, int t) {
    const char* base = (const char*)x + (size_t)t * (BM * DD * 4);
    const int tid = threadIdx.x;
    #pragma unroll
    for (int it = 0; it < (BM * XSTR_W) / NTHR; ++it) {   // 30
        int idx = it * NTHR + tid;
        int r = idx / XSTR_W;
        int c = idx - r * XSTR_W;
        uint32_t sz = (c < DD) ? 4u : 0u;
        const char* src = base + (size_t)r * (DD * 4) + (size_t)(sz ? c : 0) * 4;
        cp4(sdst + (uint32_t)idx * 4u, src, sz);
    }
}

__global__ void __launch_bounds__(NTHR, 2)
fourier_mma_kernel(const float* __restrict__ x, float* __restrict__ out,
                   int ntiles) {
    const int tid  = threadIdx.x;
    const int wid  = tid >> 5;
    const int lane = tid & 31;
    const int mwarp = wid >> 1;     // 0..3 -> rows [mwarp*16, +16)
    const int nhalf = wid & 1;      // 0..1 -> cols [nhalf*56, +56)
    const uint32_t sbase = smem_u32(smem);

    // ---- prologue: stage A (hi|lo contiguous) + first tile, one group ----
    for (int i = tid; i < (2 * A_IMG_BYTES) / 16; i += NTHR)
        cp16(sbase + AH_OFF + (uint32_t)i * 16u, g_Aimg + (size_t)i * 16);
    int t = blockIdx.x;
    if (t < ntiles) issue_tile(sbase + RAW0_OFF, x, t);
    CP_COMMIT();

    // ---- per-warp constant addresses ----
    const uint32_t a_off = (uint32_t)((mwarp * 16 + (lane >> 2)) * (XSTR_W * 4)
                                      + (lane & 3) * 8);
    const uint32_t bh = sbase + AH_OFF
        + (uint32_t)((nhalf * 56 + ((lane >> 4) * 8) + (lane & 7)) * ASTR
                     + ((lane >> 3) & 1) * 16);
    const uint32_t bl = bh + (AL_OFF - AH_OFF);
    const uint32_t b6h = sbase + AH_OFF
        + (uint32_t)((nhalf * 56 + 48 + (lane & 7)) * ASTR
                     + ((lane >> 3) & 1) * 16);
    const uint32_t b6l = b6h + (AL_OFF - AH_OFF);

    int buf = 0;
    #pragma unroll 1
    for (; t < ntiles; t += GRID) {
        const int tn = t + GRID;
        if (tn < ntiles) {
            issue_tile(sbase + (buf ? RAW0_OFF : RAW1_OFF), x, tn);
            CP_COMMIT();
            CP_WAIT1();
        } else {
            CP_WAIT0();
        }
        __syncthreads();   // raw[buf] (and A on first iter) visible to all

        // ---- mainloop over K ----
        float acc[7][4];
        #pragma unroll
        for (int nt = 0; nt < 7; ++nt)
            #pragma unroll
            for (int i = 0; i < 4; ++i) acc[nt][i] = 0.0f;

        const uint32_t rb = sbase + (buf ? RAW1_OFF : RAW0_OFF) + a_off;
        #pragma unroll 1
        for (int kt = 0; kt < 7; ++kt) {
            const uint32_t ka = rb + (uint32_t)kt * 64u;
            float2 p0 = lds64(ka);
            float2 p1 = lds64(ka + 8 * XSTR_W * 4);
            float2 p2 = lds64(ka + 32);
            float2 p3 = lds64(ka + 8 * XSTR_W * 4 + 32);
            uint32_t aH[4], aL[4];
            split2(p0.x, p0.y, aH[0], aL[0]);
            split2(p1.x, p1.y, aH[1], aL[1]);
            split2(p2.x, p2.y, aH[2], aL[2]);
            split2(p3.x, p3.y, aH[3], aL[3]);

            const uint32_t ko = (uint32_t)kt * 32u;
            uint32_t bH[12], bL[12];
            ldsm_x4(bH + 0, bh + ko);
            ldsm_x4(bH + 4, bh + 16 * ASTR + ko);
            ldsm_x4(bH + 8, bh + 32 * ASTR + ko);
            ldsm_x4(bL + 0, bl + ko);
            ldsm_x4(bL + 4, bl + 16 * ASTR + ko);
            ldsm_x4(bL + 8, bl + 32 * ASTR + ko);

            #pragma unroll
            for (int pr = 0; pr < 3; ++pr) {
                mma_bf16(acc[2*pr+0], aH, bH + 4*pr + 0);
                mma_bf16(acc[2*pr+0], aH, bL + 4*pr + 0);
                mma_bf16(acc[2*pr+0], aL, bH + 4*pr + 0);
                mma_bf16(acc[2*pr+1], aH, bH + 4*pr + 2);
                mma_bf16(acc[2*pr+1], aH, bL + 4*pr + 2);
                mma_bf16(acc[2*pr+1], aL, bH + 4*pr + 2);
            }
            if (nhalf == 0) {
                uint32_t c6h[2], c6l[2];
                ldsm_x2(c6h, b6h + ko);
                ldsm_x2(c6l, b6l + ko);
                mma_bf16(acc[6], aH, c6h);
                mma_bf16(acc[6], aH, c6l);
                mma_bf16(acc[6], aL, c6h);
            }
        }

        // ---- epilogue: direct predicated stores ----
        {
            const size_t ob = (size_t)t * BM * KO;
            const int r0 = mwarp * 16 + (lane >> 2);
            #pragma unroll
            for (int nt = 0; nt < 7; ++nt) {
                const int col = nhalf * 56 + nt * 8 + (lane & 3) * 2;
                if (col < KO) {
                    out[ob + (size_t)r0 * KO + col]       = acc[nt][0];
                    out[ob + (size_t)(r0 + 8) * KO + col] = acc[nt][2];
                    if (col + 1 < KO) {
                        out[ob + (size_t)r0 * KO + col + 1]       = acc[nt][1];
                        out[ob + (size_t)(r0 + 8) * KO + col + 1] = acc[nt][3];
                    }
                }
            }
        }
        __syncthreads();   // all warps done with raw[buf] before it is refilled
        buf ^= 1;
    }
}

// ---------------------------------------------------------------------------
// Launch
// ---------------------------------------------------------------------------
extern "C" void kernel_launch(void* const* d_in, const int* in_sizes, int n_in,
                              void* d_out, int out_size) {
    const float* x   = (const float*)d_in[0];
    const float* Wre = (const float*)d_in[1];
    const float* Wim = (const float*)d_in[2];
    const float* ReJ = (const float*)d_in[3];
    const float* ImJ = (const float*)d_in[4];
    float* out = (float*)d_out;

    const int B = in_sizes[0] / DD;       // 262144
    const int ntiles = B / BM;            // 4096

    const int build_smem = (20402 + 404) * (int)sizeof(float);   // 83224
    cudaFuncSetAttribute(build_A_kernel,
                         cudaFuncAttributeMaxDynamicSharedMemorySize, build_smem);
    build_A_kernel<<<52, 128, build_smem>>>(Wre, Wim, ReJ, ImJ);

    cudaFuncSetAttribute(fourier_mma_kernel,
                         cudaFuncAttributeMaxDynamicSharedMemorySize, SMEM_BYTES);
    fourier_mma_kernel<<<GRID, NTHR, SMEM_BYTES>>>(x, out, ntiles);
    (void)n_in; (void)out_size;
}

// round 5
// speedup vs baseline: 2.0091x; 1.2484x over previous
#include <cuda_runtime.h>
#include <cuda_bf16.h>
#include <cstdint>

// ---------------------------------------------------------------------------
// Problem constants
// ---------------------------------------------------------------------------
#define DD    101                 // inner dim (x cols)
#define KO    101                 // output cols
#define BM    64                  // batch rows per tile
#define NTHR  256
#define NROWS 104                 // A rows padded (13*8)
#define ASTR  240                 // A smem row stride bytes (120 bf16)
#define A_IMG_BYTES (NROWS * ASTR)        // 24960 per hi/lo

#define TILE_BYTES (BM * DD * 4)          // 25856, 16-mult
#define RAW_SLOT   26112                  // tile + 256 pad (zeroed)

// smem layout (bytes)
#define RAW0_OFF 0
#define RAW1_OFF RAW_SLOT                 // 26112
#define AH_OFF   (2 * RAW_SLOT)           // 52224
#define AL_OFF   (AH_OFF + A_IMG_BYTES)   // 77184
#define MBAR_OFF (AH_OFF + 2 * A_IMG_BYTES)  // 102144
#define SMEM_BYTES 102400

#define GRID 296                          // 2 CTAs/SM on 148 SMs

__device__ __align__(16) unsigned char g_Aimg[2 * A_IMG_BYTES];

// ---------------------------------------------------------------------------
// Helpers
// ---------------------------------------------------------------------------
__device__ __forceinline__ uint32_t smem_u32(const void* p) {
    uint32_t a;
    asm("{ .reg .u64 t; cvta.to.shared.u64 t, %1; cvt.u32.u64 %0, t; }"
        : "=r"(a) : "l"(p));
    return a;
}
__device__ __forceinline__ void mbar_init(uint32_t m, uint32_t cnt) {
    asm volatile("mbarrier.init.shared.b64 [%0], %1;" :: "r"(m), "r"(cnt) : "memory");
}
__device__ __forceinline__ void mbar_expect_tx(uint32_t m, uint32_t bytes) {
    asm volatile("mbarrier.arrive.expect_tx.shared.b64 _, [%0], %1;"
                 :: "r"(m), "r"(bytes) : "memory");
}
__device__ __forceinline__ void mbar_wait(uint32_t m, uint32_t parity) {
    asm volatile(
        "{\n\t.reg .pred P;\n"
        "W_%=:\n\t"
        "mbarrier.try_wait.parity.acquire.cta.shared::cta.b64 P, [%0], %1;\n\t"
        "@!P bra W_%=;\n\t}"
        :: "r"(m), "r"(parity) : "memory");
}
__device__ __forceinline__ void bulk_g2s(uint32_t dst, const void* src,
                                         uint32_t bytes, uint32_t m) {
    asm volatile(
        "cp.async.bulk.shared::cta.global.mbarrier::complete_tx::bytes "
        "[%0], [%1], %2, [%3];"
        :: "r"(dst), "l"(src), "r"(bytes), "r"(m) : "memory");
}
__device__ __forceinline__ float ldsf(uint32_t a) {
    float v;
    asm volatile("ld.shared.f32 %0, [%1];" : "=f"(v) : "r"(a));
    return v;
}
__device__ __forceinline__ void ldsm_x4(uint32_t* r, uint32_t addr) {
    asm volatile("ldmatrix.sync.aligned.m8n8.x4.shared.b16 {%0,%1,%2,%3}, [%4];"
                 : "=r"(r[0]), "=r"(r[1]), "=r"(r[2]), "=r"(r[3]) : "r"(addr));
}
__device__ __forceinline__ void ldsm_x2(uint32_t* r, uint32_t addr) {
    asm volatile("ldmatrix.sync.aligned.m8n8.x2.shared.b16 {%0,%1}, [%2];"
                 : "=r"(r[0]), "=r"(r[1]) : "r"(addr));
}
__device__ __forceinline__ void mma_bf16(float* c, const uint32_t* a,
                                         const uint32_t* b) {
    asm volatile(
        "mma.sync.aligned.m16n8k16.row.col.f32.bf16.bf16.f32 "
        "{%0,%1,%2,%3}, {%4,%5,%6,%7}, {%8,%9}, {%0,%1,%2,%3};"
        : "+f"(c[0]), "+f"(c[1]), "+f"(c[2]), "+f"(c[3])
        : "r"(a[0]), "r"(a[1]), "r"(a[2]), "r"(a[3]), "r"(b[0]), "r"(b[1]));
}
// fp32 pair -> bf16x2 hi + bf16x2 lo (residual)
__device__ __forceinline__ void split2(float f0, float f1,
                                       uint32_t& hi, uint32_t& lo) {
    asm("cvt.rn.bf16x2.f32 %0, %1, %2;" : "=r"(hi) : "f"(f1), "f"(f0));
    float l0 = f0 - __uint_as_float(hi << 16);
    float l1 = f1 - __uint_as_float(hi & 0xffff0000u);
    asm("cvt.rn.bf16x2.f32 %0, %1, %2;" : "=r"(lo) : "f"(l1), "f"(l0));
}

// ---------------------------------------------------------------------------
// Kernel 1: fold constants -> combined operator -> bf16 hi/lo image
// (row-major [n][k], 240B stride, zero-padded). smem-staged inputs.
// A[n,d] = ( sum_m Wre[n,m]*ReJ[m,d] - Wim[n,m]*ImJ[m,d] ) / 101
// ---------------------------------------------------------------------------
extern __shared__ float bsm[];
__global__ void build_A_kernel(const float* __restrict__ Wre,
                               const float* __restrict__ Wim,
                               const float* __restrict__ ReJ,
                               const float* __restrict__ ImJ) {
    float* sRe = bsm;
    float* sIm = bsm + 10201;
    float* sW  = bsm + 20402;         // [2 rows Wre][2 rows Wim]
    const int tid = threadIdx.x;      // 128
    const int n0  = blockIdx.x * 2;   // 52 blocks

    for (int i = tid; i < 10201; i += 128) { sRe[i] = ReJ[i]; sIm[i] = ImJ[i]; }
    for (int i = tid; i < 2 * DD; i += 128) {
        int j = i / DD, m = i - j * DD, n = n0 + j;
        sW[j * DD + m]          = (n < KO) ? Wre[n * DD + m] : 0.0f;
        sW[2 * DD + j * DD + m] = (n < KO) ? Wim[n * DD + m] : 0.0f;
    }
    __syncthreads();

    const int d = tid;
    if (d >= ASTR / 2) return;
    #pragma unroll 1
    for (int j = 0; j < 2; ++j) {
        const int n = n0 + j;
        float a = 0.0f;
        if (n < KO && d < DD) {
            float a0 = 0.f, a1 = 0.f;
            #pragma unroll 1
            for (int m = 0; m + 2 <= DD; m += 2) {
                a0 = fmaf(sW[j*DD+m],         sRe[m*DD+d],     a0);
                a0 = fmaf(-sW[2*DD+j*DD+m],   sIm[m*DD+d],     a0);
                a1 = fmaf(sW[j*DD+m+1],       sRe[(m+1)*DD+d], a1);
                a1 = fmaf(-sW[2*DD+j*DD+m+1], sIm[(m+1)*DD+d], a1);
            }
            a0 = fmaf(sW[j*DD+DD-1],       sRe[(DD-1)*DD+d], a0);
            a0 = fmaf(-sW[2*DD+j*DD+DD-1], sIm[(DD-1)*DD+d], a0);
            a = (a0 + a1) * (1.0f / 101.0f);
        }
        __nv_bfloat16 hi = __float2bfloat16(a);
        __nv_bfloat16 lo = __float2bfloat16(a - __bfloat162float(hi));
        *(__nv_bfloat16*)(g_Aimg + n * ASTR + d * 2)               = hi;
        *(__nv_bfloat16*)(g_Aimg + A_IMG_BYTES + n * ASTR + d * 2) = lo;
    }
}

// ---------------------------------------------------------------------------
// Kernel 2: persistent GEMM. Bulk-copy double-buffered flat x tiles,
// in-register bf16 split, term-grouped MMAs (dependency distance 7).
// ---------------------------------------------------------------------------
extern __shared__ unsigned char smem[];

__global__ void __launch_bounds__(NTHR, 2)
fourier_mma_kernel(const float* __restrict__ x, float* __restrict__ out,
                   int ntiles) {
    const int tid   = threadIdx.x;
    const int wid   = tid >> 5;
    const int lane  = tid & 31;
    const int mwarp = wid >> 1;     // rows [mwarp*16, +16)
    const int nhalf = wid & 1;      // cols [nhalf*56, +56)
    const uint32_t sbase = smem_u32(smem);
    const uint32_t mb0 = sbase + MBAR_OFF;
    const uint32_t mb1 = sbase + MBAR_OFF + 8;

    // zero the pad tails (K-tail overreads land here; must be finite)
    for (int i = tid; i < (RAW_SLOT - TILE_BYTES) / 4; i += NTHR) {
        *(uint32_t*)(smem + RAW0_OFF + TILE_BYTES + i * 4) = 0;
        *(uint32_t*)(smem + RAW1_OFF + TILE_BYTES + i * 4) = 0;
    }
    if (tid == 0) { mbar_init(mb0, 1); mbar_init(mb1, 1); }
    __syncthreads();

    int t = blockIdx.x;
    if (tid == 0) {   // prologue: A image + first tile into buf0
        mbar_expect_tx(mb0, 2 * A_IMG_BYTES + TILE_BYTES);
        bulk_g2s(sbase + AH_OFF, g_Aimg, 2 * A_IMG_BYTES, mb0);
        bulk_g2s(sbase + RAW0_OFF, (const char*)x + (size_t)t * TILE_BYTES,
                 TILE_BYTES, mb0);
    }

    // per-warp constant addresses
    const uint32_t ra = (uint32_t)((mwarp * 16 + (lane >> 2)) * DD
                                   + (lane & 3) * 2) * 4u;
    const uint32_t bh = sbase + AH_OFF
        + (uint32_t)((nhalf * 56 + ((lane >> 4) * 8) + (lane & 7)) * ASTR
                     + ((lane >> 3) & 1) * 16);
    const uint32_t bl = bh + (AL_OFF - AH_OFF);
    const uint32_t b6h = sbase + AH_OFF
        + (uint32_t)((nhalf * 56 + 48 + (lane & 7)) * ASTR
                     + ((lane >> 3) & 1) * 16);
    const uint32_t b6l = b6h + (AL_OFF - AH_OFF);

    int buf = 0;
    uint32_t par0 = 0, par1 = 0;
    #pragma unroll 1
    for (; t < ntiles; t += GRID) {
        const int tn = t + GRID;
        const uint32_t mb_cur = buf ? mb1 : mb0;
        if (tn < ntiles && tid == 0) {     // prefetch next tile into other buf
            const uint32_t mb_nxt = buf ? mb0 : mb1;
            mbar_expect_tx(mb_nxt, TILE_BYTES);
            bulk_g2s(sbase + (buf ? RAW0_OFF : RAW1_OFF),
                     (const char*)x + (size_t)tn * TILE_BYTES, TILE_BYTES, mb_nxt);
        }
        if (buf) { mbar_wait(mb1, par1); par1 ^= 1; }
        else     { mbar_wait(mb0, par0); par0 ^= 1; }

        // ---- mainloop ----
        float acc[7][4];
        #pragma unroll
        for (int nt = 0; nt < 7; ++nt)
            #pragma unroll
            for (int i = 0; i < 4; ++i) acc[nt][i] = 0.0f;

        const uint32_t rb = sbase + (buf ? RAW1_OFF : RAW0_OFF) + ra;
        #pragma unroll 1
        for (int kt = 0; kt < 7; ++kt) {
            const uint32_t ka = rb + (uint32_t)kt * 64u;
            // a-frags: rows (r, r+8), k-cols (2c, 2c+1) and (+8)
            float f0 = ldsf(ka);
            float f1 = ldsf(ka + 4);
            float f2 = ldsf(ka + DD * 8 * 4);
            float f3 = ldsf(ka + DD * 8 * 4 + 4);
            float f4 = ldsf(ka + 32);
            float f5 = ldsf(ka + 36);
            float f6 = ldsf(ka + DD * 8 * 4 + 32);
            float f7 = ldsf(ka + DD * 8 * 4 + 36);
            uint32_t aH[4], aL[4];
            split2(f0, f1, aH[0], aL[0]);
            split2(f2, f3, aH[1], aL[1]);
            split2(f4, f5, aH[2], aL[2]);
            split2(f6, f7, aH[3], aL[3]);

            const uint32_t ko = (uint32_t)kt * 32u;
            uint32_t bH[14], bL[14];
            ldsm_x4(bH + 0, bh + ko);
            ldsm_x4(bH + 4, bh + 16 * ASTR + ko);
            ldsm_x4(bH + 8, bh + 32 * ASTR + ko);
            ldsm_x4(bL + 0, bl + ko);
            ldsm_x4(bL + 4, bl + 16 * ASTR + ko);
            ldsm_x4(bL + 8, bl + 32 * ASTR + ko);
            if (nhalf == 0) {
                ldsm_x2(bH + 12, b6h + ko);
                ldsm_x2(bL + 12, b6l + ko);
            }

            // term-grouped: every acc touched once per group -> dep distance 7
            #pragma unroll
            for (int nt = 0; nt < 6; ++nt) mma_bf16(acc[nt], aH, bH + 2*nt);
            if (nhalf == 0)                mma_bf16(acc[6], aH, bH + 12);
            #pragma unroll
            for (int nt = 0; nt < 6; ++nt) mma_bf16(acc[nt], aH, bL + 2*nt);
            if (nhalf == 0)                mma_bf16(acc[6], aH, bL + 12);
            #pragma unroll
            for (int nt = 0; nt < 6; ++nt) mma_bf16(acc[nt], aL, bH + 2*nt);
            if (nhalf == 0)                mma_bf16(acc[6], aL, bH + 12);
        }

        // ---- epilogue: direct stores (8 consecutive floats per lane-quad) ----
        {
            const size_t ob = (size_t)t * BM * KO;
            const int r0 = mwarp * 16 + (lane >> 2);
            #pragma unroll
            for (int nt = 0; nt < 7; ++nt) {
                const int col = nhalf * 56 + nt * 8 + (lane & 3) * 2;
                if (col < KO) {
                    out[ob + (size_t)r0 * KO + col]       = acc[nt][0];
                    out[ob + (size_t)(r0 + 8) * KO + col] = acc[nt][2];
                    if (col + 1 < KO) {
                        out[ob + (size_t)r0 * KO + col + 1]       = acc[nt][1];
                        out[ob + (size_t)(r0 + 8) * KO + col + 1] = acc[nt][3];
                    }
                }
            }
        }
        __syncthreads();   // all warps done with raw[buf] before it refills
        buf ^= 1;
    }
}

// ---------------------------------------------------------------------------
// Launch
// ---------------------------------------------------------------------------
extern "C" void kernel_launch(void* const* d_in, const int* in_sizes, int n_in,
                              void* d_out, int out_size) {
    const float* x   = (const float*)d_in[0];
    const float* Wre = (const float*)d_in[1];
    const float* Wim = (const float*)d_in[2];
    const float* ReJ = (const float*)d_in[3];
    const float* ImJ = (const float*)d_in[4];
    float* out = (float*)d_out;

    const int B = in_sizes[0] / DD;       // 262144
    const int ntiles = B / BM;            // 4096

    const int build_smem = (20402 + 404) * (int)sizeof(float);
    cudaFuncSetAttribute(build_A_kernel,
                         cudaFuncAttributeMaxDynamicSharedMemorySize, build_smem);
    build_A_kernel<<<52, 128, build_smem>>>(Wre, Wim, ReJ, ImJ);

    cudaFuncSetAttribute(fourier_mma_kernel,
                         cudaFuncAttributeMaxDynamicSharedMemorySize, SMEM_BYTES);
    fourier_mma_kernel<<<GRID, NTHR, SMEM_BYTES>>>(x, out, ntiles);
    (void)n_in; (void)out_size;
}